// round 1
// baseline (speedup 1.0000x reference)
#include <cuda_runtime.h>

#define Bx 16
#define NN 256
#define MM 256
#define DD 256
#define UU 256

// scratch (device globals — no allocations allowed)
__device__ float g_encp[Bx * MM * UU];   // enc_proj [B,M,U]
__device__ float g_decp[Bx * NN * UU];   // dec_proj [B,N,U]

__device__ __forceinline__ float tanh_ap(float x) {
    float y;
    asm("tanh.approx.f32 %0, %1;" : "=f"(y) : "f"(x));
    return y;
}

// ---------------------------------------------------------------------------
// Projection GEMM: C[4096 x 256] = A[4096 x 256] * W[256 x 256] + bias
// 64x64 tile, BK=16, 256 threads, 4x4 microtile per thread.
// ---------------------------------------------------------------------------
__global__ __launch_bounds__(256) void proj_gemm(const float* __restrict__ A,
                                                 const float* __restrict__ W,
                                                 const float* __restrict__ bias,
                                                 int which)
{
    float* C = which ? g_decp : g_encp;

    __shared__ float As[16 * 68];   // transposed A tile, stride 68 (16B aligned, low conflict)
    __shared__ float Ws[16 * 64];   // W tile row-major

    const int tid = threadIdx.x;
    const int tm = tid >> 4;        // 0..15
    const int tn = tid & 15;        // 0..15
    const int row0 = blockIdx.y * 64;
    const int col0 = blockIdx.x * 64;

    const int ar  = tid >> 2;       // 0..63
    const int ac4 = tid & 3;        // 0..3
    const int wr  = tid >> 4;       // 0..15
    const int wc4 = tid & 15;       // 0..15

    float c[4][4] = {};

    for (int kt = 0; kt < 256; kt += 16) {
        float4 a = *(const float4*)(A + (size_t)(row0 + ar) * 256 + kt + ac4 * 4);
        float4 w = *(const float4*)(W + (size_t)(kt + wr) * 256 + col0 + wc4 * 4);
        __syncthreads();
        As[(ac4 * 4 + 0) * 68 + ar] = a.x;
        As[(ac4 * 4 + 1) * 68 + ar] = a.y;
        As[(ac4 * 4 + 2) * 68 + ar] = a.z;
        As[(ac4 * 4 + 3) * 68 + ar] = a.w;
        *(float4*)(Ws + wr * 64 + wc4 * 4) = w;
        __syncthreads();
        #pragma unroll
        for (int k = 0; k < 16; k++) {
            float4 av = *(float4*)(As + k * 68 + tm * 4);
            float4 wv = *(float4*)(Ws + k * 64 + tn * 4);
            float am[4] = {av.x, av.y, av.z, av.w};
            float wn[4] = {wv.x, wv.y, wv.z, wv.w};
            #pragma unroll
            for (int i = 0; i < 4; i++)
                #pragma unroll
                for (int j = 0; j < 4; j++)
                    c[i][j] = fmaf(am[i], wn[j], c[i][j]);
        }
    }

    float4 bv = *(const float4*)(bias + col0 + tn * 4);
    float bb[4] = {bv.x, bv.y, bv.z, bv.w};
    #pragma unroll
    for (int i = 0; i < 4; i++) {
        float4 o;
        o.x = c[i][0] + bb[0];
        o.y = c[i][1] + bb[1];
        o.z = c[i][2] + bb[2];
        o.w = c[i][3] + bb[3];
        *(float4*)(C + (size_t)(row0 + tm * 4 + i) * 256 + col0 + tn * 4) = o;
    }
}

// ---------------------------------------------------------------------------
// Fused attention kernel: logits (tanh core) + softmax + context.
// Block = (b, tile of 16 n-rows). 256 threads = 8 warps, 2 n-rows per warp.
// Lanes span u (float4): d-rows and v live in registers; enc_proj chunks
// staged through SMEM. Per-m logit finished with a 5-shuffle reduction.
// ---------------------------------------------------------------------------
__global__ __launch_bounds__(256) void attn_kernel(const float* __restrict__ enc,
                                                   const float* __restrict__ v_w,
                                                   float* __restrict__ out_ctx,
                                                   float* __restrict__ out_w)
{
    extern __shared__ float smem[];
    float* sE = smem;                   // 64*256 floats (chunk of enc_proj / enc)
    float* sD = smem + 64 * 256;        // 16*256 floats (dec_proj tile)
    float* sL = sD + 16 * 256;          // 16*256 floats (logits -> weights)

    const int tid  = threadIdx.x;
    const int warp = tid >> 5;
    const int lane = tid & 31;
    const int b  = blockIdx.y;
    const int nt = blockIdx.x;          // 0..15
    const int ln0 = warp * 2;
    const int ln1 = ln0 + 1;
    const int gn0 = nt * 16 + ln0;
    const int gn1 = gn0 + 1;

    // stage dec_proj tile
    {
        const float4* dsrc = (const float4*)(g_decp + (size_t)(b * NN + nt * 16) * UU);
        float4* sD4 = (float4*)sD;
        for (int i = tid; i < 16 * 64; i += 256) sD4[i] = dsrc[i];
    }
    __syncthreads();

    // per-warp registers: d-rows (2 n) and v, lane covers u = 4*lane.. and 128+4*lane..
    float4 d0a = ((float4*)(sD + ln0 * 256))[lane];
    float4 d0b = ((float4*)(sD + ln0 * 256))[32 + lane];
    float4 d1a = ((float4*)(sD + ln1 * 256))[lane];
    float4 d1b = ((float4*)(sD + ln1 * 256))[32 + lane];
    float4 va  = ((const float4*)v_w)[lane];
    float4 vb  = ((const float4*)v_w)[32 + lane];

    float4* sE4 = (float4*)sE;

    // ---- phase 1: logits ----
    for (int mc = 0; mc < 4; mc++) {
        __syncthreads();
        const float4* esrc = (const float4*)(g_encp + (size_t)(b * MM + mc * 64) * UU);
        for (int i = tid; i < 64 * 64; i += 256) sE4[i] = esrc[i];
        __syncthreads();
        for (int lm = 0; lm < 64; lm++) {
            float4 ea = sE4[lm * 64 + lane];
            float4 eb = sE4[lm * 64 + 32 + lane];
            float s0, s1;
            s0 = va.x * tanh_ap(ea.x + d0a.x);
            s0 = fmaf(va.y, tanh_ap(ea.y + d0a.y), s0);
            s0 = fmaf(va.z, tanh_ap(ea.z + d0a.z), s0);
            s0 = fmaf(va.w, tanh_ap(ea.w + d0a.w), s0);
            s0 = fmaf(vb.x, tanh_ap(eb.x + d0b.x), s0);
            s0 = fmaf(vb.y, tanh_ap(eb.y + d0b.y), s0);
            s0 = fmaf(vb.z, tanh_ap(eb.z + d0b.z), s0);
            s0 = fmaf(vb.w, tanh_ap(eb.w + d0b.w), s0);
            s1 = va.x * tanh_ap(ea.x + d1a.x);
            s1 = fmaf(va.y, tanh_ap(ea.y + d1a.y), s1);
            s1 = fmaf(va.z, tanh_ap(ea.z + d1a.z), s1);
            s1 = fmaf(va.w, tanh_ap(ea.w + d1a.w), s1);
            s1 = fmaf(vb.x, tanh_ap(eb.x + d1b.x), s1);
            s1 = fmaf(vb.y, tanh_ap(eb.y + d1b.y), s1);
            s1 = fmaf(vb.z, tanh_ap(eb.z + d1b.z), s1);
            s1 = fmaf(vb.w, tanh_ap(eb.w + d1b.w), s1);
            #pragma unroll
            for (int o = 16; o > 0; o >>= 1) {
                s0 += __shfl_xor_sync(0xFFFFFFFFu, s0, o);
                s1 += __shfl_xor_sync(0xFFFFFFFFu, s1, o);
            }
            if (lane == 0) {
                sL[ln0 * 256 + mc * 64 + lm] = s0;
                sL[ln1 * 256 + mc * 64 + lm] = s1;
            }
        }
    }
    __syncthreads();

    // ---- phase 2: softmax over m (v_b omitted: softmax is shift-invariant) ----
    #pragma unroll
    for (int r = 0; r < 2; r++) {
        const int ln = ln0 + r;
        const int gn = gn0 + r;
        float vals[8];
        float mx = -1e30f;
        #pragma unroll
        for (int k = 0; k < 8; k++) {
            vals[k] = sL[ln * 256 + k * 32 + lane];
            mx = fmaxf(mx, vals[k]);
        }
        #pragma unroll
        for (int o = 16; o > 0; o >>= 1) mx = fmaxf(mx, __shfl_xor_sync(0xFFFFFFFFu, mx, o));
        float s = 0.f;
        #pragma unroll
        for (int k = 0; k < 8; k++) {
            vals[k] = __expf(vals[k] - mx);
            s += vals[k];
        }
        #pragma unroll
        for (int o = 16; o > 0; o >>= 1) s += __shfl_xor_sync(0xFFFFFFFFu, s, o);
        float inv = 1.f / s;
        #pragma unroll
        for (int k = 0; k < 8; k++) {
            float w = vals[k] * inv;
            sL[ln * 256 + k * 32 + lane] = w;
            out_w[(size_t)(b * NN + gn) * MM + k * 32 + lane] = w;
        }
    }

    // ---- phase 3: context = weights @ enc ----
    float4 c0a = {0, 0, 0, 0}, c0b = {0, 0, 0, 0};
    float4 c1a = {0, 0, 0, 0}, c1b = {0, 0, 0, 0};
    for (int mc = 0; mc < 4; mc++) {
        __syncthreads();
        const float4* esrc = (const float4*)(enc + (size_t)(b * MM + mc * 64) * DD);
        for (int i = tid; i < 64 * 64; i += 256) sE4[i] = esrc[i];
        __syncthreads();
        for (int lm = 0; lm < 64; lm++) {
            const int m = mc * 64 + lm;
            float w0 = sL[ln0 * 256 + m];
            float w1 = sL[ln1 * 256 + m];
            float4 ea = sE4[lm * 64 + lane];
            float4 eb = sE4[lm * 64 + 32 + lane];
            c0a.x = fmaf(w0, ea.x, c0a.x);
            c0a.y = fmaf(w0, ea.y, c0a.y);
            c0a.z = fmaf(w0, ea.z, c0a.z);
            c0a.w = fmaf(w0, ea.w, c0a.w);
            c0b.x = fmaf(w0, eb.x, c0b.x);
            c0b.y = fmaf(w0, eb.y, c0b.y);
            c0b.z = fmaf(w0, eb.z, c0b.z);
            c0b.w = fmaf(w0, eb.w, c0b.w);
            c1a.x = fmaf(w1, ea.x, c1a.x);
            c1a.y = fmaf(w1, ea.y, c1a.y);
            c1a.z = fmaf(w1, ea.z, c1a.z);
            c1a.w = fmaf(w1, ea.w, c1a.w);
            c1b.x = fmaf(w1, eb.x, c1b.x);
            c1b.y = fmaf(w1, eb.y, c1b.y);
            c1b.z = fmaf(w1, eb.z, c1b.z);
            c1b.w = fmaf(w1, eb.w, c1b.w);
        }
    }
    {
        float4* o0 = (float4*)(out_ctx + (size_t)(b * NN + gn0) * DD);
        o0[lane] = c0a;
        o0[32 + lane] = c0b;
        float4* o1 = (float4*)(out_ctx + (size_t)(b * NN + gn1) * DD);
        o1[lane] = c1a;
        o1[32 + lane] = c1b;
    }
}

extern "C" void kernel_launch(void* const* d_in, const int* in_sizes, int n_in,
                              void* d_out, int out_size)
{
    const float* enc = (const float*)d_in[0];
    const float* dec = (const float*)d_in[1];
    const float* W1  = (const float*)d_in[2];
    const float* b1  = (const float*)d_in[3];
    const float* W2  = (const float*)d_in[4];
    const float* b2  = (const float*)d_in[5];
    const float* vw  = (const float*)d_in[6];
    // d_in[7] = v_b: constant shift, cancels in softmax -> unused.

    float* out_ctx = (float*)d_out;                              // [B,N,D]
    float* out_w   = (float*)d_out + (size_t)Bx * NN * DD;       // [B,N,M,1]

    cudaFuncSetAttribute(attn_kernel, cudaFuncAttributeMaxDynamicSharedMemorySize, 98304);

    dim3 pg(4, 64);
    proj_gemm<<<pg, 256>>>(enc, W1, b1, 0);
    proj_gemm<<<pg, 256>>>(dec, W2, b2, 1);

    attn_kernel<<<dim3(16, 16), 256, 98304>>>(enc, vw, out_ctx, out_w);
}